// round 15
// baseline (speedup 1.0000x reference)
#include <cuda_runtime.h>
#include <cuda_bf16.h>
#include <math.h>
#include <stdint.h>

// ---------------- problem constants ----------------
#define NLEV 3
#define MAXHW 65536
#define TOPK 1000
#define NTOT 3000              // 3 * TOPK
#define NW 47                  // ceil(3000/64)
#define NMS_TH 0.6f
#define CONF_TH 0.05f
#define HSTR 257               // bank-skewed hist stride

// ---------------- device scratch (no allocations allowed) ----------------
__device__ unsigned            g_bits [NLEV][MAXHW];
__device__ int                 g_label[NLEV][MAXHW];
__device__ int                 g_cand [NLEV][MAXHW];
__device__ unsigned            t_bits [NTOT];
__device__ int                 t_label[NTOT];
__device__ float               t_box  [NTOT][4];
__device__ float               s_score[NTOT];
__device__ int                 s_label[NTOT];
__device__ float               s_box  [NTOT][4];
__device__ unsigned long long  g_mask [NTOT][NW];
__device__ int                 g_dummy;

__constant__ int   c_HW[3]   = {65536, 16384, 4096};
__constant__ int   c_W[3]    = {256, 128, 64};
__constant__ float c_strd[3] = {8.0f, 16.0f, 32.0f};

// ---------------- kernels ----------------

__device__ __forceinline__ float sigm(float x) { return 1.0f / (1.0f + expf(-x)); }

// marker no-op (slot alignment: 2 markers put topk_level in ncu capture slot #4)
__global__ void marker_kernel(int v) { if (threadIdx.x == 1025) g_dummy = v; }

// fused decode, high-MLP: 1 thread/pixel, class loop in batches of 16
__global__ void __launch_bounds__(256) decode_all_kernel(
        const float* __restrict__ cls0,
        const float* __restrict__ cls1,
        const float* __restrict__ cls2,
        const float* __restrict__ ctn0,
        const float* __restrict__ ctn1,
        const float* __restrict__ ctn2) {
    int blk = blockIdx.x;
    int lv; const float* cls; const float* ctn; int HW;
    if (blk < 256)      { lv = 0; cls = cls0; ctn = ctn0; HW = 65536; }
    else if (blk < 320) { lv = 1; cls = cls1; ctn = ctn1; HW = 16384; blk -= 256; }
    else                { lv = 2; cls = cls2; ctn = ctn2; HW = 4096;  blk -= 320; }
    int i = blk * 256 + threadIdx.x;
    if (i >= HW) return;

    const float* p = cls + i;
    float m = -1e30f;
    int lab = 0;
    #pragma unroll
    for (int c0 = 0; c0 < 80; c0 += 16) {
        float v[16];
        #pragma unroll
        for (int k = 0; k < 16; k++) v[k] = p[(c0 + k) * HW];  // 16 independent loads
        #pragma unroll
        for (int k = 0; k < 16; k++)
            if (v[k] > m) { m = v[k]; lab = c0 + k; }          // in-order: first-max
    }

    float sc = sqrtf(sigm(m) * sigm(ctn[i]));
    g_bits[lv][i]  = __float_as_uint(sc);   // sc in (0,1): bits monotone in value
    g_label[lv][i] = lab;
}

// One block per level: THREE refinement passes with WARP-PRIVATE bank-skewed
// histograms (no cross-warp bank serialization), compact, rank, emit topk.
__global__ void __launch_bounds__(1024) topk_level_kernel(
        const float* __restrict__ reg0,
        const float* __restrict__ reg1,
        const float* __restrict__ reg2,
        const float* __restrict__ scales) {
    int lv = blockIdx.x;
    const float* reg = (lv == 0) ? reg0 : (lv == 1) ? reg1 : reg2;
    int HW = c_HW[lv], W = c_W[lv];
    float stride = c_strd[lv];
    int tid = threadIdx.x;
    int wid = tid >> 5;
    int n4 = HW >> 2;
    const uint4* b4 = (const uint4*)g_bits[lv];

    __shared__ unsigned h32[32 * HSTR];   // warp-private hists, bank-skewed
    __shared__ unsigned suf[256];
    __shared__ int      sh_B;
    __shared__ unsigned sh_above;
    __shared__ int      sh_cnt;
    __shared__ unsigned long long skey[1024];

    unsigned* myh = &h32[wid * HSTR];

    // ---- pass 1: coarse hist over bits>>24 ----
    for (int z = tid; z < 32 * HSTR; z += 1024) h32[z] = 0u;
    __syncthreads();
    for (int i = tid; i < n4; i += 1024) {
        uint4 v = b4[i];
        atomicAdd(&myh[v.x >> 24], 1u);
        atomicAdd(&myh[v.y >> 24], 1u);
        atomicAdd(&myh[v.z >> 24], 1u);
        atomicAdd(&myh[v.w >> 24], 1u);
    }
    __syncthreads();
    if (tid < 256) {
        unsigned s = 0;
        #pragma unroll
        for (int w = 0; w < 32; w++) s += h32[w * HSTR + tid];
        suf[tid] = s;
    }
    __syncthreads();
    for (int off = 1; off < 256; off <<= 1) {
        unsigned add = (tid < 256 && tid + off < 256) ? suf[tid + off] : 0u;
        __syncthreads();
        if (tid < 256) suf[tid] += add;
        __syncthreads();
    }
    if (tid < 256) {
        bool ok  = suf[tid] >= (unsigned)TOPK;
        bool okn = (tid == 255) ? false : (suf[tid + 1] >= (unsigned)TOPK);
        if (ok && !okn) { sh_B = tid; sh_above = (tid == 255) ? 0u : suf[tid + 1]; }
    }
    __syncthreads();
    int B1 = sh_B;
    unsigned above1 = sh_above;

    // ---- pass 2: hist over (bits>>16)&0xFF within prefix B1 ----
    __syncthreads();
    for (int z = tid; z < 32 * HSTR; z += 1024) h32[z] = 0u;
    __syncthreads();
    for (int i = tid; i < n4; i += 1024) {
        uint4 v = b4[i];
        if ((int)(v.x >> 24) == B1) atomicAdd(&myh[(v.x >> 16) & 0xFF], 1u);
        if ((int)(v.y >> 24) == B1) atomicAdd(&myh[(v.y >> 16) & 0xFF], 1u);
        if ((int)(v.z >> 24) == B1) atomicAdd(&myh[(v.z >> 16) & 0xFF], 1u);
        if ((int)(v.w >> 24) == B1) atomicAdd(&myh[(v.w >> 16) & 0xFF], 1u);
    }
    __syncthreads();
    if (tid < 256) {
        unsigned s = 0;
        #pragma unroll
        for (int w = 0; w < 32; w++) s += h32[w * HSTR + tid];
        suf[tid] = s;
    }
    __syncthreads();
    for (int off = 1; off < 256; off <<= 1) {
        unsigned add = (tid < 256 && tid + off < 256) ? suf[tid + off] : 0u;
        __syncthreads();
        if (tid < 256) suf[tid] += add;
        __syncthreads();
    }
    if (tid < 256) {
        bool ok  = above1 + suf[tid] >= (unsigned)TOPK;
        bool okn = (tid == 255) ? false : (above1 + suf[tid + 1] >= (unsigned)TOPK);
        if (ok && !okn) {
            sh_B = ((B1 << 8) | tid);
            sh_above = above1 + ((tid == 255) ? 0u : suf[tid + 1]);
        }
    }
    __syncthreads();
    int B2 = sh_B;
    unsigned above2 = sh_above;

    // ---- pass 3: hist over (bits>>8)&0xFF within prefix B2 ----
    __syncthreads();
    for (int z = tid; z < 32 * HSTR; z += 1024) h32[z] = 0u;
    __syncthreads();
    for (int i = tid; i < n4; i += 1024) {
        uint4 v = b4[i];
        if ((int)(v.x >> 16) == B2) atomicAdd(&myh[(v.x >> 8) & 0xFF], 1u);
        if ((int)(v.y >> 16) == B2) atomicAdd(&myh[(v.y >> 8) & 0xFF], 1u);
        if ((int)(v.z >> 16) == B2) atomicAdd(&myh[(v.z >> 8) & 0xFF], 1u);
        if ((int)(v.w >> 16) == B2) atomicAdd(&myh[(v.w >> 8) & 0xFF], 1u);
    }
    __syncthreads();
    if (tid < 256) {
        unsigned s = 0;
        #pragma unroll
        for (int w = 0; w < 32; w++) s += h32[w * HSTR + tid];
        suf[tid] = s;
    }
    __syncthreads();
    for (int off = 1; off < 256; off <<= 1) {
        unsigned add = (tid < 256 && tid + off < 256) ? suf[tid + off] : 0u;
        __syncthreads();
        if (tid < 256) suf[tid] += add;
        __syncthreads();
    }
    if (tid < 256) {
        bool ok  = above2 + suf[tid] >= (unsigned)TOPK;
        bool okn = (tid == 255) ? false : (above2 + suf[tid + 1] >= (unsigned)TOPK);
        if (ok && !okn) sh_B = ((B2 << 8) | tid);
    }
    __syncthreads();
    unsigned thresh = ((unsigned)sh_B) << 8;

    // ---- compact ----
    if (tid == 0) sh_cnt = 0;
    __syncthreads();
    for (int i4 = tid; i4 < n4; i4 += 1024) {
        uint4 v = b4[i4];
        int i = i4 * 4;
        if (v.x >= thresh) g_cand[lv][atomicAdd(&sh_cnt, 1)] = i;
        if (v.y >= thresh) g_cand[lv][atomicAdd(&sh_cnt, 1)] = i + 1;
        if (v.z >= thresh) g_cand[lv][atomicAdd(&sh_cnt, 1)] = i + 2;
        if (v.w >= thresh) g_cand[lv][atomicAdd(&sh_cnt, 1)] = i + 3;
    }
    __syncthreads();
    int ncand = sh_cnt;

    // ---- rank candidates (value desc, index asc) and emit topk rows ----
    float scl = scales[lv];
    for (int cbase = 0; cbase < ncand; cbase += 1024) {
        int c = cbase + tid;
        bool active = (c < ncand);
        unsigned mybits = 0; int myidx = 0;
        unsigned long long mykey = 0;
        if (active) {
            myidx  = g_cand[lv][c];
            mybits = g_bits[lv][myidx];
            mykey  = ((unsigned long long)mybits << 32) | (unsigned)(~(unsigned)myidx);
        }
        int rank = 0;
        for (int base = 0; base < ncand; base += 1024) {
            int j = base + tid;
            unsigned long long k = 0;
            if (j < ncand) {
                int ji = g_cand[lv][j];
                k = ((unsigned long long)g_bits[lv][ji] << 32) | (unsigned)(~(unsigned)ji);
            }
            __syncthreads();
            skey[tid] = k;
            __syncthreads();
            int lim = min(1024, ncand - base);
            if (active)
                for (int t = 0; t < lim; t++) rank += (skey[t] > mykey) ? 1 : 0;
        }
        if (active && rank < TOPK) {
            int o = lv * TOPK + rank;
            t_bits[o]  = mybits;
            t_label[o] = g_label[lv][myidx];
            int x = myidx % W, y = myidx / W;
            float ax = ((float)x + 0.5f) * stride;
            float ay = ((float)y + 0.5f) * stride;
            float r0 = fmaxf(reg[0 * HW + myidx] * scl, 0.0f) * stride;
            float r1 = fmaxf(reg[1 * HW + myidx] * scl, 0.0f) * stride;
            float r2 = fmaxf(reg[2 * HW + myidx] * scl, 0.0f) * stride;
            float r3 = fmaxf(reg[3 * HW + myidx] * scl, 0.0f) * stride;
            t_box[o][0] = ax - r0; t_box[o][1] = ay - r1;
            t_box[o][2] = ax + r2; t_box[o][3] = ay + r3;
        }
        __syncthreads();
    }
}

// Global stable argsort(-scores) via 3-way MERGE of the per-level sorted runs.
__global__ void __launch_bounds__(1000) rank_merge_kernel() {
    __shared__ unsigned sm[NTOT];
    int lv = blockIdx.x;            // 3 blocks, one per level
    int p  = threadIdx.x;           // 1000 threads = within-level position
    for (int i = p; i < NTOT; i += 1000) sm[i] = t_bits[i];
    __syncthreads();

    int g = lv * TOPK + p;
    unsigned b = sm[g];
    int rank = p;
    #pragma unroll
    for (int m = 0; m < NLEV; m++) {
        if (m == lv) continue;
        const unsigned* seg = &sm[m * TOPK];
        int lo = 0, hi = TOPK;
        if (m < lv) {
            while (lo < hi) { int mid = (lo + hi) >> 1;
                if (seg[mid] >= b) lo = mid + 1; else hi = mid; }
        } else {
            while (lo < hi) { int mid = (lo + hi) >> 1;
                if (seg[mid] >  b) lo = mid + 1; else hi = mid; }
        }
        rank += lo;
    }
    s_score[rank] = __uint_as_float(b);
    s_label[rank] = t_label[g];
    s_box[rank][0] = t_box[g][0];
    s_box[rank][1] = t_box[g][1];
    s_box[rank][2] = t_box[g][2];
    s_box[rank][3] = t_box[g][3];
}

// suppression bitmask: bit j (j>i) set iff IoU(i,j) > 0.6
__global__ void mask_kernel() {
    int w  = blockIdx.x;                 // word 0..46  (j in [64w, 64w+64))
    int by = blockIdx.y;                 // i-block     (i in [256by, 256by+256))
    if (w < 4 * by) return;              // all j < all i in this block: never read
    __shared__ float jb[64][4];
    __shared__ float ja[64];
    int jlim = min(64, NTOT - w * 64);
    if ((int)threadIdx.x < jlim) {
        int j = w * 64 + threadIdx.x;
        float x1 = s_box[j][0], y1 = s_box[j][1], x2 = s_box[j][2], y2 = s_box[j][3];
        jb[threadIdx.x][0] = x1; jb[threadIdx.x][1] = y1;
        jb[threadIdx.x][2] = x2; jb[threadIdx.x][3] = y2;
        ja[threadIdx.x] = (x2 - x1) * (y2 - y1);
    }
    __syncthreads();
    int i = by * 256 + threadIdx.x;
    if (i >= NTOT) return;
    float ix1 = s_box[i][0], iy1 = s_box[i][1], ix2 = s_box[i][2], iy2 = s_box[i][3];
    float ia = (ix2 - ix1) * (iy2 - iy1);
    unsigned long long bits = 0;
    for (int b = 0; b < jlim; b++) {
        int j = w * 64 + b;
        if (j > i) {
            float xx1 = fmaxf(ix1, jb[b][0]);
            float yy1 = fmaxf(iy1, jb[b][1]);
            float xx2 = fminf(ix2, jb[b][2]);
            float yy2 = fminf(iy2, jb[b][3]);
            float ww = fmaxf(1e-10f, xx2 - xx1);
            float hh = fmaxf(1e-10f, yy2 - yy1);
            float inter = ww * hh;
            float iou = inter / (ia + ja[b] - inter + 1e-14f);
            if (iou > NMS_TH) bits |= (1ull << b);
        }
    }
    g_mask[i][w] = bits;
}

__device__ __forceinline__ unsigned long long warp_or64(unsigned long long v) {
    #pragma unroll
    for (int o = 16; o; o >>= 1) v |= __shfl_xor_sync(0xFFFFFFFFu, v, o);
    return v;
}

// Pipelined greedy NMS with SPARSE intra-word scan (proven round-13 structure).
__global__ void __launch_bounds__(768) nms_finalize_kernel(float* __restrict__ out) {
    __shared__ unsigned long long  sh_kept[NW];
    __shared__ unsigned long long  sh_remv[NW];
    __shared__ volatile int        sh_flag[NW];
    __shared__ unsigned long long  colbuf[24][64];
    int tid  = threadIdx.x;           // 768
    int warp = tid >> 5, lane = tid & 31;
    if (tid < NW) sh_flag[tid] = 0;
    __syncthreads();

    int w0 = warp * 2;
    int w1 = w0 + 1;                   // may be 47 (invalid for warp 23)
    bool has1 = (w1 < NW);
    int last = has1 ? w1 : w0;

    unsigned long long acc0 = 0ull, acc1 = 0ull;
    int rA = lane, rB = lane + 32;     // row offsets within a 64-block

    for (int c = 0; c <= last; c++) {
        int base = c * 64;
        unsigned long long m00 = (base + rA < NTOT) ? g_mask[base + rA][w0] : 0ull;
        unsigned long long m01 = (base + rB < NTOT) ? g_mask[base + rB][w0] : 0ull;
        unsigned long long m10 = 0ull, m11 = 0ull;
        if (has1) {
            m10 = (base + rA < NTOT) ? g_mask[base + rA][w1] : 0ull;
            m11 = (base + rB < NTOT) ? g_mask[base + rB][w1] : 0ull;
        }
        unsigned long long kept;
        if (c == w0 || c == w1) {
            unsigned long long mA = (c == w0) ? m00 : m10;
            unsigned long long mB = (c == w0) ? m01 : m11;
            colbuf[warp][lane]      = mA;
            colbuf[warp][lane + 32] = mB;
            unsigned balA = __ballot_sync(0xFFFFFFFFu, mA != 0ull);  // rows 0..31
            unsigned balB = __ballot_sync(0xFFFFFFFFu, mB != 0ull);  // rows 32..63
            __syncwarp();
            unsigned long long r = warp_or64((c == w0) ? acc0 : acc1);
            unsigned long long k0 = 0ull;
            if (lane == 0) {
                unsigned long long nz = (unsigned long long)balA
                                      | ((unsigned long long)balB << 32);
                int lim = min(64, NTOT - base);
                while (nz) {
                    int b = __ffsll((long long)nz) - 1;
                    nz &= nz - 1;
                    if (!((r >> b) & 1ull)) r |= colbuf[warp][b];
                }
                k0 = ~r;
                if (lim < 64) k0 &= (1ull << lim) - 1ull;
                sh_remv[c] = r;
                sh_kept[c] = k0;
                __threadfence_block();
                sh_flag[c] = 1;
            }
            kept = __shfl_sync(0xFFFFFFFFu, k0, 0);
            __syncwarp();
        } else {
            while (sh_flag[c] == 0) {}
            __threadfence_block();
            kept = sh_kept[c];
        }
        if (c < w0) {
            acc0 |= (((kept >> rA) & 1ull) ? m00 : 0ull)
                  | (((kept >> rB) & 1ull) ? m01 : 0ull);
        }
        if (has1 && c < w1) {
            acc1 |= (((kept >> rA) & 1ull) ? m10 : 0ull)
                  | (((kept >> rB) & 1ull) ? m11 : 0ull);
        }
    }
    __syncthreads();

    // fused finalize: [boxes 12000][scores 3000][labels 3000][keep 3000] all f32
    for (int i = tid; i < NTOT; i += 768) {
        out[i * 4 + 0] = s_box[i][0];
        out[i * 4 + 1] = s_box[i][1];
        out[i * 4 + 2] = s_box[i][2];
        out[i * 4 + 3] = s_box[i][3];
        float sc = s_score[i];
        out[12000 + i] = sc;
        out[15000 + i] = (float)s_label[i];
        bool kp = !((sh_remv[i >> 6] >> (i & 63)) & 1ull) && (sc > CONF_TH);
        out[18000 + i] = kp ? 1.0f : 0.0f;
    }
}

// ---------------- launch ----------------
extern "C" void kernel_launch(void* const* d_in, const int* in_sizes, int n_in,
                              void* d_out, int out_size) {
    const float *cls[3], *reg[3], *ctn[3], *scales;
    if (in_sizes[1] == 262144) {
        cls[0] = (const float*)d_in[0]; reg[0] = (const float*)d_in[1]; ctn[0] = (const float*)d_in[2];
        cls[1] = (const float*)d_in[3]; reg[1] = (const float*)d_in[4]; ctn[1] = (const float*)d_in[5];
        cls[2] = (const float*)d_in[6]; reg[2] = (const float*)d_in[7]; ctn[2] = (const float*)d_in[8];
        scales = (const float*)d_in[9];
    } else if (in_sizes[3] == 262144) {
        cls[0] = (const float*)d_in[0]; cls[1] = (const float*)d_in[1]; cls[2] = (const float*)d_in[2];
        reg[0] = (const float*)d_in[3]; reg[1] = (const float*)d_in[4]; reg[2] = (const float*)d_in[5];
        ctn[0] = (const float*)d_in[6]; ctn[1] = (const float*)d_in[7]; ctn[2] = (const float*)d_in[8];
        scales = (const float*)d_in[9];
    } else {
        cls[0] = (const float*)d_in[0]; cls[1] = (const float*)d_in[1]; cls[2] = (const float*)d_in[2];
        ctn[0] = (const float*)d_in[3]; ctn[1] = (const float*)d_in[4]; ctn[2] = (const float*)d_in[5];
        reg[0] = (const float*)d_in[6]; reg[1] = (const float*)d_in[7]; reg[2] = (const float*)d_in[8];
        scales = (const float*)d_in[9];
    }

    // 2 markers => topk_level lands in ncu capture slot #4
    marker_kernel<<<1, 32>>>(1);
    marker_kernel<<<1, 32>>>(2);
    decode_all_kernel<<<256 + 64 + 16, 256>>>(cls[0], cls[1], cls[2],
                                              ctn[0], ctn[1], ctn[2]);
    topk_level_kernel<<<3, 1024>>>(reg[0], reg[1], reg[2], scales);
    rank_merge_kernel<<<3, 1000>>>();
    {
        dim3 grid(NW, (NTOT + 255) / 256);
        mask_kernel<<<grid, 256>>>();
    }
    nms_finalize_kernel<<<1, 768>>>((float*)d_out);
}

// round 16
// speedup vs baseline: 1.0649x; 1.0649x over previous
#include <cuda_runtime.h>
#include <cuda_bf16.h>
#include <math.h>
#include <stdint.h>

// ---------------- problem constants ----------------
#define NLEV 3
#define MAXHW 65536
#define TOPK 1000
#define NTOT 3000              // 3 * TOPK
#define NW 47                  // ceil(3000/64)
#define NMS_TH 0.6f
#define CONF_TH 0.05f
#define SORTN 2048             // bitonic sort capacity

// ---------------- device scratch (no allocations allowed) ----------------
__device__ unsigned            g_bits [NLEV][MAXHW];
__device__ int                 g_label[NLEV][MAXHW];
__device__ int                 g_cand [NLEV][MAXHW];
__device__ unsigned            t_bits [NTOT];
__device__ int                 t_label[NTOT];
__device__ float               t_box  [NTOT][4];
__device__ float               s_score[NTOT];
__device__ int                 s_label[NTOT];
__device__ float               s_box  [NTOT][4];
__device__ unsigned long long  g_mask [NTOT][NW];
__device__ int                 g_dummy;

__constant__ int   c_HW[3]   = {65536, 16384, 4096};
__constant__ int   c_W[3]    = {256, 128, 64};
__constant__ float c_strd[3] = {8.0f, 16.0f, 32.0f};

// ---------------- kernels ----------------

__device__ __forceinline__ float sigm(float x) { return 1.0f / (1.0f + expf(-x)); }

// marker no-op (slot alignment: 2 markers put topk_level in ncu capture slot #4)
__global__ void marker_kernel(int v) { if (threadIdx.x == 1025) g_dummy = v; }

// fused decode, high-MLP: 1 thread/pixel, class loop in batches of 16
__global__ void __launch_bounds__(256) decode_all_kernel(
        const float* __restrict__ cls0,
        const float* __restrict__ cls1,
        const float* __restrict__ cls2,
        const float* __restrict__ ctn0,
        const float* __restrict__ ctn1,
        const float* __restrict__ ctn2) {
    int blk = blockIdx.x;
    int lv; const float* cls; const float* ctn; int HW;
    if (blk < 256)      { lv = 0; cls = cls0; ctn = ctn0; HW = 65536; }
    else if (blk < 320) { lv = 1; cls = cls1; ctn = ctn1; HW = 16384; blk -= 256; }
    else                { lv = 2; cls = cls2; ctn = ctn2; HW = 4096;  blk -= 320; }
    int i = blk * 256 + threadIdx.x;
    if (i >= HW) return;

    const float* p = cls + i;
    float m = -1e30f;
    int lab = 0;
    #pragma unroll
    for (int c0 = 0; c0 < 80; c0 += 16) {
        float v[16];
        #pragma unroll
        for (int k = 0; k < 16; k++) v[k] = p[(c0 + k) * HW];  // 16 independent loads
        #pragma unroll
        for (int k = 0; k < 16; k++)
            if (v[k] > m) { m = v[k]; lab = c0 + k; }          // in-order: first-max
    }

    float sc = sqrtf(sigm(m) * sigm(ctn[i]));
    g_bits[lv][i]  = __float_as_uint(sc);   // sc in (0,1): bits monotone in value
    g_label[lv][i] = lab;
}

// One block per level: THREE 256-bucket refinement passes (exact 24-bit bucket
// threshold -> ncand ~ 1000+eps), compact, bitonic-sort, emit topk.
__global__ void __launch_bounds__(1024) topk_level_kernel(
        const float* __restrict__ reg0,
        const float* __restrict__ reg1,
        const float* __restrict__ reg2,
        const float* __restrict__ scales) {
    int lv = blockIdx.x;
    const float* reg = (lv == 0) ? reg0 : (lv == 1) ? reg1 : reg2;
    int HW = c_HW[lv], W = c_W[lv];
    float stride = c_strd[lv];
    int tid = threadIdx.x;
    int n4 = HW >> 2;
    const uint4* b4 = (const uint4*)g_bits[lv];

    __shared__ unsigned hist[256];
    __shared__ unsigned suf[256];
    __shared__ int      sh_B;
    __shared__ unsigned sh_above;
    __shared__ int      sh_cnt;
    __shared__ unsigned long long skey[SORTN];

    // ---- pass 1: coarse hist over bits>>24 ----
    if (tid < 256) hist[tid] = 0u;
    __syncthreads();
    for (int i = tid; i < n4; i += 1024) {
        uint4 v = b4[i];
        atomicAdd(&hist[v.x >> 24], 1u);
        atomicAdd(&hist[v.y >> 24], 1u);
        atomicAdd(&hist[v.z >> 24], 1u);
        atomicAdd(&hist[v.w >> 24], 1u);
    }
    __syncthreads();
    if (tid < 256) suf[tid] = hist[tid];
    __syncthreads();
    for (int off = 1; off < 256; off <<= 1) {
        unsigned add = (tid < 256 && tid + off < 256) ? suf[tid + off] : 0u;
        __syncthreads();
        if (tid < 256) suf[tid] += add;
        __syncthreads();
    }
    if (tid < 256) {
        bool ok  = suf[tid] >= (unsigned)TOPK;
        bool okn = (tid == 255) ? false : (suf[tid + 1] >= (unsigned)TOPK);
        if (ok && !okn) { sh_B = tid; sh_above = (tid == 255) ? 0u : suf[tid + 1]; }
    }
    __syncthreads();
    int B1 = sh_B;
    unsigned above1 = sh_above;

    // ---- pass 2: hist over (bits>>16)&0xFF within prefix B1 ----
    if (tid < 256) hist[tid] = 0u;
    __syncthreads();
    for (int i = tid; i < n4; i += 1024) {
        uint4 v = b4[i];
        if ((int)(v.x >> 24) == B1) atomicAdd(&hist[(v.x >> 16) & 0xFF], 1u);
        if ((int)(v.y >> 24) == B1) atomicAdd(&hist[(v.y >> 16) & 0xFF], 1u);
        if ((int)(v.z >> 24) == B1) atomicAdd(&hist[(v.z >> 16) & 0xFF], 1u);
        if ((int)(v.w >> 24) == B1) atomicAdd(&hist[(v.w >> 16) & 0xFF], 1u);
    }
    __syncthreads();
    if (tid < 256) suf[tid] = hist[tid];
    __syncthreads();
    for (int off = 1; off < 256; off <<= 1) {
        unsigned add = (tid < 256 && tid + off < 256) ? suf[tid + off] : 0u;
        __syncthreads();
        if (tid < 256) suf[tid] += add;
        __syncthreads();
    }
    if (tid < 256) {
        bool ok  = above1 + suf[tid] >= (unsigned)TOPK;
        bool okn = (tid == 255) ? false : (above1 + suf[tid + 1] >= (unsigned)TOPK);
        if (ok && !okn) {
            sh_B = ((B1 << 8) | tid);
            sh_above = above1 + ((tid == 255) ? 0u : suf[tid + 1]);
        }
    }
    __syncthreads();
    int B2 = sh_B;
    unsigned above2 = sh_above;

    // ---- pass 3: hist over (bits>>8)&0xFF within prefix B2 ----
    if (tid < 256) hist[tid] = 0u;
    __syncthreads();
    for (int i = tid; i < n4; i += 1024) {
        uint4 v = b4[i];
        if ((int)(v.x >> 16) == B2) atomicAdd(&hist[(v.x >> 8) & 0xFF], 1u);
        if ((int)(v.y >> 16) == B2) atomicAdd(&hist[(v.y >> 8) & 0xFF], 1u);
        if ((int)(v.z >> 16) == B2) atomicAdd(&hist[(v.z >> 8) & 0xFF], 1u);
        if ((int)(v.w >> 16) == B2) atomicAdd(&hist[(v.w >> 8) & 0xFF], 1u);
    }
    __syncthreads();
    if (tid < 256) suf[tid] = hist[tid];
    __syncthreads();
    for (int off = 1; off < 256; off <<= 1) {
        unsigned add = (tid < 256 && tid + off < 256) ? suf[tid + off] : 0u;
        __syncthreads();
        if (tid < 256) suf[tid] += add;
        __syncthreads();
    }
    if (tid < 256) {
        bool ok  = above2 + suf[tid] >= (unsigned)TOPK;
        bool okn = (tid == 255) ? false : (above2 + suf[tid + 1] >= (unsigned)TOPK);
        if (ok && !okn) sh_B = ((B2 << 8) | tid);
    }
    __syncthreads();
    unsigned thresh = ((unsigned)sh_B) << 8;

    // ---- compact ----
    if (tid == 0) sh_cnt = 0;
    __syncthreads();
    for (int i4 = tid; i4 < n4; i4 += 1024) {
        uint4 v = b4[i4];
        int i = i4 * 4;
        if (v.x >= thresh) g_cand[lv][atomicAdd(&sh_cnt, 1)] = i;
        if (v.y >= thresh) g_cand[lv][atomicAdd(&sh_cnt, 1)] = i + 1;
        if (v.z >= thresh) g_cand[lv][atomicAdd(&sh_cnt, 1)] = i + 2;
        if (v.w >= thresh) g_cand[lv][atomicAdd(&sh_cnt, 1)] = i + 3;
    }
    __syncthreads();
    int ncand = sh_cnt;
    float scl = scales[lv];

    if (ncand <= SORTN) {
        // ---- bitonic sort DESC on unique 64-bit keys (bits<<32 | ~idx) ----
        for (int e = tid; e < SORTN; e += 1024) {
            unsigned long long k = 0ull;           // pad keys sort last (real keys >= 2^32)
            if (e < ncand) {
                int ji = g_cand[lv][e];
                k = ((unsigned long long)g_bits[lv][ji] << 32) | (unsigned)(~(unsigned)ji);
            }
            skey[e] = k;
        }
        __syncthreads();
        for (int kk = 2; kk <= SORTN; kk <<= 1) {
            for (int j = kk >> 1; j > 0; j >>= 1) {
                for (int e = tid; e < SORTN; e += 1024) {
                    int p = e ^ j;
                    if (p > e) {
                        unsigned long long a = skey[e], b = skey[p];
                        bool desc = ((e & kk) == 0);
                        bool sw = desc ? (a < b) : (a > b);
                        if (sw) { skey[e] = b; skey[p] = a; }
                    }
                }
                __syncthreads();
            }
        }
        // emit: sorted position == rank (threshold guarantees ncand >= TOPK)
        if (tid < TOPK && tid < ncand) {
            unsigned long long k = skey[tid];
            unsigned mybits = (unsigned)(k >> 32);
            int myidx = (int)(~(unsigned)(k & 0xFFFFFFFFull));
            int o = lv * TOPK + tid;
            t_bits[o]  = mybits;
            t_label[o] = g_label[lv][myidx];
            int x = myidx % W, y = myidx / W;
            float ax = ((float)x + 0.5f) * stride;
            float ay = ((float)y + 0.5f) * stride;
            float r0 = fmaxf(reg[0 * HW + myidx] * scl, 0.0f) * stride;
            float r1 = fmaxf(reg[1 * HW + myidx] * scl, 0.0f) * stride;
            float r2 = fmaxf(reg[2 * HW + myidx] * scl, 0.0f) * stride;
            float r3 = fmaxf(reg[3 * HW + myidx] * scl, 0.0f) * stride;
            t_box[o][0] = ax - r0; t_box[o][1] = ay - r1;
            t_box[o][2] = ax + r2; t_box[o][3] = ay + r3;
        }
    } else {
        // ---- fallback (ncand > SORTN): proven rank-count path ----
        for (int cbase = 0; cbase < ncand; cbase += 1024) {
            int c = cbase + tid;
            bool active = (c < ncand);
            unsigned mybits = 0; int myidx = 0;
            unsigned long long mykey = 0;
            if (active) {
                myidx  = g_cand[lv][c];
                mybits = g_bits[lv][myidx];
                mykey  = ((unsigned long long)mybits << 32) | (unsigned)(~(unsigned)myidx);
            }
            int rank = 0;
            for (int base = 0; base < ncand; base += 1024) {
                int j = base + tid;
                unsigned long long k = 0;
                if (j < ncand) {
                    int ji = g_cand[lv][j];
                    k = ((unsigned long long)g_bits[lv][ji] << 32) | (unsigned)(~(unsigned)ji);
                }
                __syncthreads();
                skey[tid] = k;
                __syncthreads();
                int lim = min(1024, ncand - base);
                if (active)
                    for (int t = 0; t < lim; t++) rank += (skey[t] > mykey) ? 1 : 0;
            }
            if (active && rank < TOPK) {
                int o = lv * TOPK + rank;
                t_bits[o]  = mybits;
                t_label[o] = g_label[lv][myidx];
                int x = myidx % W, y = myidx / W;
                float ax = ((float)x + 0.5f) * stride;
                float ay = ((float)y + 0.5f) * stride;
                float r0 = fmaxf(reg[0 * HW + myidx] * scl, 0.0f) * stride;
                float r1 = fmaxf(reg[1 * HW + myidx] * scl, 0.0f) * stride;
                float r2 = fmaxf(reg[2 * HW + myidx] * scl, 0.0f) * stride;
                float r3 = fmaxf(reg[3 * HW + myidx] * scl, 0.0f) * stride;
                t_box[o][0] = ax - r0; t_box[o][1] = ay - r1;
                t_box[o][2] = ax + r2; t_box[o][3] = ay + r3;
            }
            __syncthreads();
        }
    }
}

// Global stable argsort(-scores) via 3-way MERGE of the per-level sorted runs.
__global__ void __launch_bounds__(1000) rank_merge_kernel() {
    __shared__ unsigned sm[NTOT];
    int lv = blockIdx.x;            // 3 blocks, one per level
    int p  = threadIdx.x;           // 1000 threads = within-level position
    for (int i = p; i < NTOT; i += 1000) sm[i] = t_bits[i];
    __syncthreads();

    int g = lv * TOPK + p;
    unsigned b = sm[g];
    int rank = p;
    #pragma unroll
    for (int m = 0; m < NLEV; m++) {
        if (m == lv) continue;
        const unsigned* seg = &sm[m * TOPK];
        int lo = 0, hi = TOPK;
        if (m < lv) {
            while (lo < hi) { int mid = (lo + hi) >> 1;
                if (seg[mid] >= b) lo = mid + 1; else hi = mid; }
        } else {
            while (lo < hi) { int mid = (lo + hi) >> 1;
                if (seg[mid] >  b) lo = mid + 1; else hi = mid; }
        }
        rank += lo;
    }
    s_score[rank] = __uint_as_float(b);
    s_label[rank] = t_label[g];
    s_box[rank][0] = t_box[g][0];
    s_box[rank][1] = t_box[g][1];
    s_box[rank][2] = t_box[g][2];
    s_box[rank][3] = t_box[g][3];
}

// suppression bitmask: bit j (j>i) set iff IoU(i,j) > 0.6
__global__ void mask_kernel() {
    int w  = blockIdx.x;                 // word 0..46  (j in [64w, 64w+64))
    int by = blockIdx.y;                 // i-block     (i in [256by, 256by+256))
    if (w < 4 * by) return;              // all j < all i in this block: never read
    __shared__ float jb[64][4];
    __shared__ float ja[64];
    int jlim = min(64, NTOT - w * 64);
    if ((int)threadIdx.x < jlim) {
        int j = w * 64 + threadIdx.x;
        float x1 = s_box[j][0], y1 = s_box[j][1], x2 = s_box[j][2], y2 = s_box[j][3];
        jb[threadIdx.x][0] = x1; jb[threadIdx.x][1] = y1;
        jb[threadIdx.x][2] = x2; jb[threadIdx.x][3] = y2;
        ja[threadIdx.x] = (x2 - x1) * (y2 - y1);
    }
    __syncthreads();
    int i = by * 256 + threadIdx.x;
    if (i >= NTOT) return;
    float ix1 = s_box[i][0], iy1 = s_box[i][1], ix2 = s_box[i][2], iy2 = s_box[i][3];
    float ia = (ix2 - ix1) * (iy2 - iy1);
    unsigned long long bits = 0;
    for (int b = 0; b < jlim; b++) {
        int j = w * 64 + b;
        if (j > i) {
            float xx1 = fmaxf(ix1, jb[b][0]);
            float yy1 = fmaxf(iy1, jb[b][1]);
            float xx2 = fminf(ix2, jb[b][2]);
            float yy2 = fminf(iy2, jb[b][3]);
            float ww = fmaxf(1e-10f, xx2 - xx1);
            float hh = fmaxf(1e-10f, yy2 - yy1);
            float inter = ww * hh;
            float iou = inter / (ia + ja[b] - inter + 1e-14f);
            if (iou > NMS_TH) bits |= (1ull << b);
        }
    }
    g_mask[i][w] = bits;
}

__device__ __forceinline__ unsigned long long warp_or64(unsigned long long v) {
    #pragma unroll
    for (int o = 16; o; o >>= 1) v |= __shfl_xor_sync(0xFFFFFFFFu, v, o);
    return v;
}

// Pipelined greedy NMS with SPARSE intra-word scan (proven round-13 structure).
__global__ void __launch_bounds__(768) nms_finalize_kernel(float* __restrict__ out) {
    __shared__ unsigned long long  sh_kept[NW];
    __shared__ unsigned long long  sh_remv[NW];
    __shared__ volatile int        sh_flag[NW];
    __shared__ unsigned long long  colbuf[24][64];
    int tid  = threadIdx.x;           // 768
    int warp = tid >> 5, lane = tid & 31;
    if (tid < NW) sh_flag[tid] = 0;
    __syncthreads();

    int w0 = warp * 2;
    int w1 = w0 + 1;                   // may be 47 (invalid for warp 23)
    bool has1 = (w1 < NW);
    int last = has1 ? w1 : w0;

    unsigned long long acc0 = 0ull, acc1 = 0ull;
    int rA = lane, rB = lane + 32;     // row offsets within a 64-block

    for (int c = 0; c <= last; c++) {
        int base = c * 64;
        unsigned long long m00 = (base + rA < NTOT) ? g_mask[base + rA][w0] : 0ull;
        unsigned long long m01 = (base + rB < NTOT) ? g_mask[base + rB][w0] : 0ull;
        unsigned long long m10 = 0ull, m11 = 0ull;
        if (has1) {
            m10 = (base + rA < NTOT) ? g_mask[base + rA][w1] : 0ull;
            m11 = (base + rB < NTOT) ? g_mask[base + rB][w1] : 0ull;
        }
        unsigned long long kept;
        if (c == w0 || c == w1) {
            unsigned long long mA = (c == w0) ? m00 : m10;
            unsigned long long mB = (c == w0) ? m01 : m11;
            colbuf[warp][lane]      = mA;
            colbuf[warp][lane + 32] = mB;
            unsigned balA = __ballot_sync(0xFFFFFFFFu, mA != 0ull);  // rows 0..31
            unsigned balB = __ballot_sync(0xFFFFFFFFu, mB != 0ull);  // rows 32..63
            __syncwarp();
            unsigned long long r = warp_or64((c == w0) ? acc0 : acc1);
            unsigned long long k0 = 0ull;
            if (lane == 0) {
                unsigned long long nz = (unsigned long long)balA
                                      | ((unsigned long long)balB << 32);
                int lim = min(64, NTOT - base);
                while (nz) {
                    int b = __ffsll((long long)nz) - 1;
                    nz &= nz - 1;
                    if (!((r >> b) & 1ull)) r |= colbuf[warp][b];
                }
                k0 = ~r;
                if (lim < 64) k0 &= (1ull << lim) - 1ull;
                sh_remv[c] = r;
                sh_kept[c] = k0;
                __threadfence_block();
                sh_flag[c] = 1;
            }
            kept = __shfl_sync(0xFFFFFFFFu, k0, 0);
            __syncwarp();
        } else {
            while (sh_flag[c] == 0) {}
            __threadfence_block();
            kept = sh_kept[c];
        }
        if (c < w0) {
            acc0 |= (((kept >> rA) & 1ull) ? m00 : 0ull)
                  | (((kept >> rB) & 1ull) ? m01 : 0ull);
        }
        if (has1 && c < w1) {
            acc1 |= (((kept >> rA) & 1ull) ? m10 : 0ull)
                  | (((kept >> rB) & 1ull) ? m11 : 0ull);
        }
    }
    __syncthreads();

    // fused finalize: [boxes 12000][scores 3000][labels 3000][keep 3000] all f32
    for (int i = tid; i < NTOT; i += 768) {
        out[i * 4 + 0] = s_box[i][0];
        out[i * 4 + 1] = s_box[i][1];
        out[i * 4 + 2] = s_box[i][2];
        out[i * 4 + 3] = s_box[i][3];
        float sc = s_score[i];
        out[12000 + i] = sc;
        out[15000 + i] = (float)s_label[i];
        bool kp = !((sh_remv[i >> 6] >> (i & 63)) & 1ull) && (sc > CONF_TH);
        out[18000 + i] = kp ? 1.0f : 0.0f;
    }
}

// ---------------- launch ----------------
extern "C" void kernel_launch(void* const* d_in, const int* in_sizes, int n_in,
                              void* d_out, int out_size) {
    const float *cls[3], *reg[3], *ctn[3], *scales;
    if (in_sizes[1] == 262144) {
        cls[0] = (const float*)d_in[0]; reg[0] = (const float*)d_in[1]; ctn[0] = (const float*)d_in[2];
        cls[1] = (const float*)d_in[3]; reg[1] = (const float*)d_in[4]; ctn[1] = (const float*)d_in[5];
        cls[2] = (const float*)d_in[6]; reg[2] = (const float*)d_in[7]; ctn[2] = (const float*)d_in[8];
        scales = (const float*)d_in[9];
    } else if (in_sizes[3] == 262144) {
        cls[0] = (const float*)d_in[0]; cls[1] = (const float*)d_in[1]; cls[2] = (const float*)d_in[2];
        reg[0] = (const float*)d_in[3]; reg[1] = (const float*)d_in[4]; reg[2] = (const float*)d_in[5];
        ctn[0] = (const float*)d_in[6]; ctn[1] = (const float*)d_in[7]; ctn[2] = (const float*)d_in[8];
        scales = (const float*)d_in[9];
    } else {
        cls[0] = (const float*)d_in[0]; cls[1] = (const float*)d_in[1]; cls[2] = (const float*)d_in[2];
        ctn[0] = (const float*)d_in[3]; ctn[1] = (const float*)d_in[4]; ctn[2] = (const float*)d_in[5];
        reg[0] = (const float*)d_in[6]; reg[1] = (const float*)d_in[7]; reg[2] = (const float*)d_in[8];
        scales = (const float*)d_in[9];
    }

    // 2 markers => topk_level lands in ncu capture slot #4
    marker_kernel<<<1, 32>>>(1);
    marker_kernel<<<1, 32>>>(2);
    decode_all_kernel<<<256 + 64 + 16, 256>>>(cls[0], cls[1], cls[2],
                                              ctn[0], ctn[1], ctn[2]);
    topk_level_kernel<<<3, 1024>>>(reg[0], reg[1], reg[2], scales);
    rank_merge_kernel<<<3, 1000>>>();
    {
        dim3 grid(NW, (NTOT + 255) / 256);
        mask_kernel<<<grid, 256>>>();
    }
    nms_finalize_kernel<<<1, 768>>>((float*)d_out);
}